// round 14
// baseline (speedup 1.0000x reference)
#include <cuda_runtime.h>
#include <cuda_bf16.h>
#include <mma.h>
#include <math.h>
#include <cstdint>

using namespace nvcuda;

#define BB   16
#define CQ   80
#define CKCH 512
#define CA   80
#define TDE  2000
#define TEN  512
#define KH1  1024
#define QH1  160
#define TEMPR 0.0005f

// ---------------- scratch ----------------
__device__ __align__(16) __nv_bfloat16 g_colk[(size_t)BB * CKCH * 3 * TEN];
__device__ __align__(16) __nv_bfloat16 g_colq[(size_t)BB * CQ   * 3 * TDE];
__device__ __align__(16) __nv_bfloat16 g_khid[(size_t)BB * KH1 * TEN];
__device__ __align__(16) __nv_bfloat16 g_qh1 [(size_t)BB * QH1 * TDE];
__device__ __align__(16) __nv_bfloat16 g_qh2 [(size_t)BB * CQ  * TDE];
__device__ __align__(16) __nv_bfloat16 g_kenc[(size_t)BB * CA  * TEN + 64];
__device__ __align__(16) __nv_bfloat16 g_qenc[(size_t)BB * CA  * TDE + 64];
__device__ __align__(16) __nv_bfloat16 g_w1k[KH1 * CKCH * 3];
__device__ __align__(16) __nv_bfloat16 g_w2k[CA * KH1];
__device__ __align__(16) __nv_bfloat16 g_w1q[QH1 * CQ * 3];
__device__ __align__(16) __nv_bfloat16 g_w2q[CA * QH1];
__device__ __align__(16) __nv_bfloat16 g_w3q[CA * CQ];
__device__ float g_qsq[BB * TDE];
__device__ float g_ksq[BB * TEN];

// ---------------- fused weight fp32->bf16 ----------------
#define W0 393216
#define W1 20480
#define W2 9600
#define W3 3200
#define W4 1600
__global__ void wcvt(const float* a0, const float* a1, const float* a2,
                     const float* a3, const float* a4,
                     __nv_bfloat16* o0, __nv_bfloat16* o1, __nv_bfloat16* o2,
                     __nv_bfloat16* o3, __nv_bfloat16* o4)
{
    int i = blockIdx.x * blockDim.x + threadIdx.x;
    const float* src; __nv_bfloat16* dst; int j = i;
    if (j < W0)                { src = a0; dst = o0; }
    else if ((j -= W0) < W1)   { src = a1; dst = o1; }
    else if ((j -= W1) < W2)   { src = a2; dst = o2; }
    else if ((j -= W2) < W3)   { src = a3; dst = o3; }
    else if ((j -= W3) < W4)   { src = a4; dst = o4; }
    else return;
    float4 v = reinterpret_cast<const float4*>(src)[j];
    __nv_bfloat162* o = reinterpret_cast<__nv_bfloat162*>(dst) + 2 * j;
    o[0] = __floats2bfloat162_rn(v.x, v.y);
    o[1] = __floats2bfloat162_rn(v.z, v.w);
}

// ---------------- im2col (k=3, pad=1) fused with fp32->bf16 ----------------
__global__ void im2col3f(const float* __restrict__ X,
                         __nv_bfloat16* __restrict__ out, int C, int T)
{
    int b = blockIdx.y;
    int idx = blockIdx.x * blockDim.x + threadIdx.x;
    int th = T >> 1;
    int total2 = C * 3 * th;
    if (idx >= total2) return;
    int tp = idx % th;
    int row = idx / th;
    int ci = row / 3, dk = row - ci * 3;
    int t = tp * 2;
    const float* Xr = X + ((size_t)b * C + ci) * T;
    int t0 = t + dk - 1, t1 = t0 + 1;
    float v0 = (t0 >= 0 && t0 < T) ? Xr[t0] : 0.f;
    float v1 = (t1 >= 0 && t1 < T) ? Xr[t1] : 0.f;
    reinterpret_cast<__nv_bfloat162*>(out + (size_t)b * C * 3 * T + (size_t)row * T)[tp]
        = __floats2bfloat162_rn(v0, v1);
}

// ---------------- cp.async helper ----------------
__device__ __forceinline__ void cp16(uint32_t d, const void* s, bool p) {
    int sz = p ? 16 : 0;
    asm volatile("cp.async.cg.shared.global [%0], [%1], 16, %2;\n"
                 :: "r"(d), "l"(s), "r"(sz) : "memory");
}

// ---------------- conv1k GEMM: BM=128, GBK=64, 3-stage, 2 CTAs/SM ----------------
#define K128 64
#define SM128 (3 * 128 * 72 * 2 + 3 * K128 * 136 * 2)   // 107520; patch aliases As

__global__ __launch_bounds__(256, 2) void gemm128(
    const __nv_bfloat16* __restrict__ Bmat,
    const __nv_bfloat16* __restrict__ W,
    const float* __restrict__ bias,
    __nv_bfloat16* __restrict__ Y,
    int Kt, int Cout, int Nn, int do_relu)
{
    extern __shared__ char sm[];
    typedef __nv_bfloat16 bf;
    bf (*As)[128][72]  = reinterpret_cast<bf(*)[128][72]>(sm);
    bf (*Bs)[K128][136] = reinterpret_cast<bf(*)[K128][136]>(sm + 3 * 128 * 72 * 2);

    const int b  = blockIdx.z;
    const int m0 = blockIdx.y * 128;
    const int n0 = blockIdx.x * 128;
    const __nv_bfloat16* Bb = Bmat + (size_t)b * Kt * Nn;
    __nv_bfloat16*       Yb = Y    + (size_t)b * Cout * Nn;

    const int tid = threadIdx.x;
    const int warp = tid >> 5, lane = tid & 31;
    const int wm = warp >> 2, wn = warp & 3;

    wmma::fragment<wmma::accumulator, 16, 16, 16, float> acc[4][2];
#pragma unroll
    for (int i = 0; i < 4; i++)
#pragma unroll
        for (int j = 0; j < 2; j++) wmma::fill_fragment(acc[i][j], 0.f);

    const int nK = Kt / K128;

    auto load_stage = [&](int st, int k0) {
#pragma unroll
        for (int i = 0; i < 4; i++) {
            int idx = tid + 256 * i;
            int m = idx >> 3, kc = idx & 7;
            uint32_t d = (uint32_t)__cvta_generic_to_shared(&As[st][m][kc * 8]);
            cp16(d, W + (size_t)(m0 + m) * Kt + k0 + kc * 8, true);
        }
#pragma unroll
        for (int i = 0; i < 4; i++) {
            int idx = tid + 256 * i;
            int r = idx >> 4, nc = idx & 15;
            uint32_t d = (uint32_t)__cvta_generic_to_shared(&Bs[st][r][nc * 8]);
            cp16(d, Bb + (size_t)(k0 + r) * Nn + n0 + nc * 8, true);
        }
        asm volatile("cp.async.commit_group;\n" ::: "memory");
    };

    load_stage(0, 0);
    load_stage(1, K128);

    for (int kt = 0; kt < nK; kt++) {
        asm volatile("cp.async.wait_group 1;\n" ::: "memory");
        __syncthreads();
        if (kt + 2 < nK) load_stage((kt + 2) % 3, (kt + 2) * K128);
        else asm volatile("cp.async.commit_group;\n" ::: "memory");
        const int st = kt % 3;
#pragma unroll
        for (int ks = 0; ks < 4; ks++) {
            wmma::fragment<wmma::matrix_a, 16, 16, 16, __nv_bfloat16, wmma::row_major> af[4];
            wmma::fragment<wmma::matrix_b, 16, 16, 16, __nv_bfloat16, wmma::row_major> bfr[2];
#pragma unroll
            for (int i = 0; i < 4; i++)
                wmma::load_matrix_sync(af[i], &As[st][wm * 64 + i * 16][ks * 16], 72);
#pragma unroll
            for (int j = 0; j < 2; j++)
                wmma::load_matrix_sync(bfr[j], &Bs[st][ks * 16][wn * 32 + j * 16], 136);
#pragma unroll
            for (int i = 0; i < 4; i++)
#pragma unroll
                for (int j = 0; j < 2; j++)
                    wmma::mma_sync(acc[i][j], af[i], bfr[j], acc[i][j]);
        }
    }
    asm volatile("cp.async.wait_group 0;\n" ::: "memory");
    __syncthreads();

    float (*patch)[16][18] = reinterpret_cast<float(*)[16][18]>(sm);
#pragma unroll
    for (int i = 0; i < 4; i++) {
#pragma unroll
        for (int j = 0; j < 2; j++) {
            wmma::store_matrix_sync(&patch[warp][0][0], acc[i][j], 18, wmma::mem_row_major);
            __syncwarp();
            int r = lane >> 1, h = lane & 1;
            int gm = m0 + wm * 64 + i * 16 + r;
            int gn = n0 + wn * 32 + j * 16 + h * 8;
            float bv = bias[gm];
            float v[8];
#pragma unroll
            for (int e = 0; e < 8; e++) {
                float x = patch[warp][r][h * 8 + e] + bv;
                v[e] = do_relu ? fmaxf(x, 0.f) : x;
            }
            __nv_bfloat162 p[4];
            p[0] = __floats2bfloat162_rn(v[0], v[1]);
            p[1] = __floats2bfloat162_rn(v[2], v[3]);
            p[2] = __floats2bfloat162_rn(v[4], v[5]);
            p[3] = __floats2bfloat162_rn(v[6], v[7]);
            *reinterpret_cast<uint4*>(Yb + (size_t)gm * Nn + gn) =
                *reinterpret_cast<uint4*>(p);
            __syncwarp();
        }
    }
}

// ---------------- small-conv GEMM: BM=64, GBK=32, 3-stage (R10-proven) ----------------
#define GBN 128
#define GBK 32

template<int BM>
__global__ __launch_bounds__(256) void gemm_bf16(
    const __nv_bfloat16* __restrict__ Bmat,
    const __nv_bfloat16* __restrict__ W,
    const float* __restrict__ bias,
    __nv_bfloat16* __restrict__ Y,
    int Kt, int Cout, int Nn, int do_relu)
{
    extern __shared__ char sm[];
    typedef __nv_bfloat16 bf;
    bf (*As)[BM][40]  = reinterpret_cast<bf(*)[BM][40]>(sm);
    bf (*Bs)[GBK][136] = reinterpret_cast<bf(*)[GBK][136]>(sm + 3 * BM * 40 * 2);
    float (*patch)[16][18] =
        reinterpret_cast<float(*)[16][18]>(sm + 3 * BM * 40 * 2 + 3 * GBK * 136 * 2);

    const int b  = blockIdx.z;
    const int m0 = blockIdx.y * BM;
    const int n0 = blockIdx.x * GBN;
    const __nv_bfloat16* Bb = Bmat + (size_t)b * Kt * Nn;
    __nv_bfloat16*       Yb = Y    + (size_t)b * Cout * Nn;

    const int tid = threadIdx.x;
    const int warp = tid >> 5, lane = tid & 31;
    const int wm = warp >> 2, wn = warp & 3;
    constexpr int FM = BM / 32;

    wmma::fragment<wmma::accumulator, 16, 16, 16, float> acc[FM][2];
#pragma unroll
    for (int i = 0; i < FM; i++)
#pragma unroll
        for (int j = 0; j < 2; j++) wmma::fill_fragment(acc[i][j], 0.f);

    const int nK = (Kt + GBK - 1) / GBK;

    auto load_stage = [&](int st, int k0) {
#pragma unroll
        for (int idx = tid; idx < BM * 4; idx += 256) {
            int m = idx >> 2, kc = idx & 3;
            int gm = m0 + m, gk = k0 + kc * 8;
            uint32_t d = (uint32_t)__cvta_generic_to_shared(&As[st][m][kc * 8]);
            cp16(d, W + (size_t)gm * Kt + gk, (gm < Cout) && (gk < Kt));
        }
#pragma unroll
        for (int i = 0; i < 2; i++) {
            int idx = tid * 2 + i;
            int r = idx >> 4, nc = idx & 15;
            int gk = k0 + r, gn = n0 + nc * 8;
            uint32_t d = (uint32_t)__cvta_generic_to_shared(&Bs[st][r][nc * 8]);
            cp16(d, Bb + (size_t)gk * Nn + gn, (gk < Kt) && (gn < Nn));
        }
        asm volatile("cp.async.commit_group;\n" ::: "memory");
    };

    load_stage(0, 0);
    load_stage(1, GBK);

    for (int kt = 0; kt < nK; kt++) {
        asm volatile("cp.async.wait_group 1;\n" ::: "memory");
        __syncthreads();
        if (kt + 2 < nK) load_stage((kt + 2) % 3, (kt + 2) * GBK);
        else asm volatile("cp.async.commit_group;\n" ::: "memory");
        const int st = kt % 3;
#pragma unroll
        for (int ks = 0; ks < 2; ks++) {
            wmma::fragment<wmma::matrix_a, 16, 16, 16, __nv_bfloat16, wmma::row_major> af[FM];
            wmma::fragment<wmma::matrix_b, 16, 16, 16, __nv_bfloat16, wmma::row_major> bfr[2];
#pragma unroll
            for (int i = 0; i < FM; i++)
                wmma::load_matrix_sync(af[i], &As[st][wm * (BM / 2) + i * 16][ks * 16], 40);
#pragma unroll
            for (int j = 0; j < 2; j++)
                wmma::load_matrix_sync(bfr[j], &Bs[st][ks * 16][wn * 32 + j * 16], 136);
#pragma unroll
            for (int i = 0; i < FM; i++)
#pragma unroll
                for (int j = 0; j < 2; j++)
                    wmma::mma_sync(acc[i][j], af[i], bfr[j], acc[i][j]);
        }
    }

#pragma unroll
    for (int i = 0; i < FM; i++) {
#pragma unroll
        for (int j = 0; j < 2; j++) {
            wmma::store_matrix_sync(&patch[warp][0][0], acc[i][j], 18, wmma::mem_row_major);
            __syncwarp();
            int r = lane >> 1, h = lane & 1;
            int gm = m0 + wm * (BM / 2) + i * 16 + r;
            int gn = n0 + wn * 32 + j * 16 + h * 8;
            if (gm < Cout && gn < Nn) {
                float bv = bias[gm];
                float v[8];
#pragma unroll
                for (int e = 0; e < 8; e++) {
                    float x = patch[warp][r][h * 8 + e] + bv;
                    v[e] = do_relu ? fmaxf(x, 0.f) : x;
                }
                __nv_bfloat162 p[4];
                p[0] = __floats2bfloat162_rn(v[0], v[1]);
                p[1] = __floats2bfloat162_rn(v[2], v[3]);
                p[2] = __floats2bfloat162_rn(v[4], v[5]);
                p[3] = __floats2bfloat162_rn(v[6], v[7]);
                *reinterpret_cast<uint4*>(Yb + (size_t)gm * Nn + gn) =
                    *reinterpret_cast<uint4*>(p);
            }
            __syncwarp();
        }
    }
}

// ---------------- squared channel norms (R10-proven scalar form) ----------------
__global__ void sqnorm_bf16(const __nv_bfloat16* __restrict__ X,
                            float* __restrict__ out, int C, int T)
{
    int b = blockIdx.y;
    int t = blockIdx.x * blockDim.x + threadIdx.x;
    if (t >= T) return;
    const __nv_bfloat16* Xb = X + (size_t)b * C * T + t;
    float s = 0.f;
    for (int c = 0; c < C; c++) {
        float v = __bfloat162float(Xb[(size_t)c * T]);
        s += v * v;
    }
    out[b * T + t] = s;
}

// ---------------- attn: wmma QK (B from L2) + smem-resident max-free dual softmax ----------------
#define AR 32
#define ATN_SMEM (6400 + 2048 + 66048)   // qs + ksq + lg = 74496

__global__ __launch_bounds__(256) void attn2(
    const __nv_bfloat16* __restrict__ qenc, const __nv_bfloat16* __restrict__ kenc,
    const float* __restrict__ qsq,  const float* __restrict__ ksq,
    const float* __restrict__ prior, float* __restrict__ out)
{
    extern __shared__ char sm[];
    typedef __nv_bfloat16 bf;
    bf (*qs)[40]    = reinterpret_cast<bf(*)[40]>(sm);
    float* ksq_s    = reinterpret_cast<float*>(sm + 6400);
    float (*lg)[516]= reinterpret_cast<float(*)[516]>(sm + 6400 + 2048);

    const int b  = blockIdx.y;
    const int t0 = blockIdx.x * AR;
    const int tid = threadIdx.x;
    const int warp = tid >> 5;

    const bf* kb = kenc + (size_t)b * CA * TEN;
    const bf* qb = qenc + (size_t)b * CA * TDE;

#pragma unroll
    for (int i = 0; i < 10; i++) {
        int idx = tid + 256 * i;
        int ch = idx >> 5, j = idx & 31;
        qs[ch][j] = qb[(size_t)ch * TDE + t0 + j];
    }
    for (int i = tid; i < TEN; i += 256) ksq_s[i] = ksq[b * TEN + i];
    __syncthreads();

    {
        wmma::fragment<wmma::accumulator, 16, 16, 16, float> acc[2][4];
#pragma unroll
        for (int i = 0; i < 2; i++)
#pragma unroll
            for (int j = 0; j < 4; j++) wmma::fill_fragment(acc[i][j], 0.f);
#pragma unroll
        for (int ks = 0; ks < 5; ks++) {
            wmma::fragment<wmma::matrix_a, 16, 16, 16, bf, wmma::col_major> af[2];
            wmma::fragment<wmma::matrix_b, 16, 16, 16, bf, wmma::row_major> bfr[4];
#pragma unroll
            for (int i = 0; i < 2; i++)
                wmma::load_matrix_sync(af[i], &qs[ks * 16][i * 16], 40);
#pragma unroll
            for (int j = 0; j < 4; j++)
                wmma::load_matrix_sync(bfr[j],
                    kb + (size_t)(ks * 16) * TEN + warp * 64 + j * 16, TEN);
#pragma unroll
            for (int i = 0; i < 2; i++)
#pragma unroll
                for (int j = 0; j < 4; j++)
                    wmma::mma_sync(acc[i][j], af[i], bfr[j], acc[i][j]);
        }
#pragma unroll
        for (int i = 0; i < 2; i++)
#pragma unroll
            for (int j = 0; j < 4; j++)
                wmma::store_matrix_sync(&lg[i * 16][warp * 64 + j * 16], acc[i][j],
                                        516, wmma::mem_row_major);
    }
    __syncthreads();

    // Max-free dual softmax, values staged in smem (low register pressure).
    // Safe without max subtraction: logits = -TEMP*dist <= 0, exp in (0,1];
    // second-pass args are ~[-26,-6], exp >= ~1e-12 — no overflow/underflow.
    const int r = tid >> 3, cl = tid & 7;
    const int gr = t0 + r;
    const bool valid = gr < TDE;
    float4* lgr = reinterpret_cast<float4*>(&lg[r][0]);
    const float4* ksq4 = reinterpret_cast<const float4*>(ksq_s);
    const float qsq_r = valid ? qsq[b * TDE + gr] : 0.f;

    // sweep 1: logits + sum(exp) fused
    float s1 = 0.f;
#pragma unroll
    for (int u = 0; u < 16; u++) {
        int i4 = cl + 8 * u;
        float4 v = lgr[i4];
        float4 k4 = ksq4[i4];
        v.x = TEMPR * (2.f * v.x - qsq_r - k4.x);
        v.y = TEMPR * (2.f * v.y - qsq_r - k4.y);
        v.z = TEMPR * (2.f * v.z - qsq_r - k4.z);
        v.w = TEMPR * (2.f * v.w - qsq_r - k4.w);
        lgr[i4] = v;
        s1 += __expf(v.x) + __expf(v.y) + __expf(v.z) + __expf(v.w);
    }
#pragma unroll
    for (int msk = 4; msk >= 1; msk >>= 1)
        s1 += __shfl_xor_sync(0xffffffffu, s1, msk);
    const float logZ = __logf(s1);

    // sweep 2: + log prior, write logprob, exp back into smem, accumulate sum
    const size_t row = ((size_t)b * TDE + gr) * TEN;
    const size_t NT = (size_t)BB * TDE * TEN;
    const float4* pr4 = reinterpret_cast<const float4*>(prior + row);
    float4* olp = reinterpret_cast<float4*>(out + NT + row);
    float s2 = 0.f;
#pragma unroll
    for (int u = 0; u < 16; u++) {
        int i4 = cl + 8 * u;
        float4 v = lgr[i4];
        if (valid) {
            float4 p = pr4[i4];
            v.x = v.x - logZ + __logf(p.x + 1e-8f);
            v.y = v.y - logZ + __logf(p.y + 1e-8f);
            v.z = v.z - logZ + __logf(p.z + 1e-8f);
            v.w = v.w - logZ + __logf(p.w + 1e-8f);
            olp[i4] = v;
        }
        float4 e;
        e.x = __expf(v.x); e.y = __expf(v.y);
        e.z = __expf(v.z); e.w = __expf(v.w);
        lgr[i4] = e;
        s2 += e.x + e.y + e.z + e.w;
    }
#pragma unroll
    for (int msk = 4; msk >= 1; msk >>= 1)
        s2 += __shfl_xor_sync(0xffffffffu, s2, msk);
    const float inv = 1.f / s2;

    // sweep 3: normalize + write attn
    float4* oat = reinterpret_cast<float4*>(out + row);
    if (valid) {
#pragma unroll
        for (int u = 0; u < 16; u++) {
            int i4 = cl + 8 * u;
            float4 e = lgr[i4];
            float4 w = { e.x * inv, e.y * inv, e.z * inv, e.w * inv };
            oat[i4] = w;
        }
    }
}

// ---------------- launch ----------------
static inline int ceil_div(int a, int b) { return (a + b - 1) / b; }

extern "C" void kernel_launch(void* const* d_in, const int* in_sizes, int n_in,
                              void* d_out, int out_size)
{
    const float* queries = (const float*)d_in[0];
    const float* keys    = (const float*)d_in[1];
    const float* prior   = (const float*)d_in[3];
    const float* kp_w1 = (const float*)d_in[4];
    const float* kp_b1 = (const float*)d_in[5];
    const float* kp_w2 = (const float*)d_in[6];
    const float* kp_b2 = (const float*)d_in[7];
    const float* qp_w1 = (const float*)d_in[8];
    const float* qp_b1 = (const float*)d_in[9];
    const float* qp_w2 = (const float*)d_in[10];
    const float* qp_b2 = (const float*)d_in[11];
    const float* qp_w3 = (const float*)d_in[12];
    const float* qp_b3 = (const float*)d_in[13];
    float* out = (float*)d_out;

    __nv_bfloat16 *colk, *colq, *khid, *qh1, *qh2, *kenc, *qenc;
    __nv_bfloat16 *w1k, *w2k, *w1q, *w2q, *w3q;
    float *qsq, *ksq;
    cudaGetSymbolAddress((void**)&colk, g_colk);
    cudaGetSymbolAddress((void**)&colq, g_colq);
    cudaGetSymbolAddress((void**)&khid, g_khid);
    cudaGetSymbolAddress((void**)&qh1,  g_qh1);
    cudaGetSymbolAddress((void**)&qh2,  g_qh2);
    cudaGetSymbolAddress((void**)&kenc, g_kenc);
    cudaGetSymbolAddress((void**)&qenc, g_qenc);
    cudaGetSymbolAddress((void**)&w1k,  g_w1k);
    cudaGetSymbolAddress((void**)&w2k,  g_w2k);
    cudaGetSymbolAddress((void**)&w1q,  g_w1q);
    cudaGetSymbolAddress((void**)&w2q,  g_w2q);
    cudaGetSymbolAddress((void**)&w3q,  g_w3q);
    cudaGetSymbolAddress((void**)&qsq,  g_qsq);
    cudaGetSymbolAddress((void**)&ksq,  g_ksq);

    const int SM64 = 3 * 64 * 40 * 2 + 3 * GBK * 136 * 2 + 8 * 16 * 18 * 4; // 50688
    cudaFuncSetAttribute(gemm128, cudaFuncAttributeMaxDynamicSharedMemorySize, SM128);
    cudaFuncSetAttribute(gemm_bf16<64>, cudaFuncAttributeMaxDynamicSharedMemorySize, SM64);
    cudaFuncSetAttribute(attn2, cudaFuncAttributeMaxDynamicSharedMemorySize, ATN_SMEM);

    // weights -> bf16 (single launch)
    wcvt<<<ceil_div(W0 + W1 + W2 + W3 + W4, 256), 256>>>(
        kp_w1, kp_w2, qp_w1, qp_w2, qp_w3, w1k, w2k, w1q, w2q, w3q);

    // fused im2col + cvt
    im2col3f<<<dim3(ceil_div(CKCH * 3 * TEN / 2, 256), BB), 256>>>(keys, colk, CKCH, TEN);
    im2col3f<<<dim3(ceil_div(CQ * 3 * TDE / 2, 256), BB), 256>>>(queries, colq, CQ, TDE);

    // conv1k: BM=128 GBK=64, 2 CTAs/SM
    gemm128<<<dim3(TEN / 128, KH1 / 128, BB), 256, SM128>>>(
        colk, w1k, kp_b1, khid, CKCH * 3, KH1, TEN, 1);

    // small convs: BM=64 (R10-proven)
    gemm_bf16<64><<<dim3(ceil_div(TEN, GBN), ceil_div(CA, 64), BB), 256, SM64>>>(
        khid, w2k, kp_b2, kenc, KH1, CA, TEN, 0);
    gemm_bf16<64><<<dim3(ceil_div(TDE, GBN), ceil_div(QH1, 64), BB), 256, SM64>>>(
        colq, w1q, qp_b1, qh1, CQ * 3, QH1, TDE, 1);
    gemm_bf16<64><<<dim3(ceil_div(TDE, GBN), ceil_div(CA, 64), BB), 256, SM64>>>(
        qh1, w2q, qp_b2, qh2, QH1, CA, TDE, 1);
    gemm_bf16<64><<<dim3(ceil_div(TDE, GBN), ceil_div(CA, 64), BB), 256, SM64>>>(
        qh2, w3q, qp_b3, qenc, CQ, CA, TDE, 0);

    // squared norms (R10-proven scalar launch config)
    sqnorm_bf16<<<dim3(ceil_div(TDE, 256), BB), 256>>>(qenc, qsq, CA, TDE);
    sqnorm_bf16<<<dim3(ceil_div(TEN, 256), BB), 256>>>(kenc, ksq, CA, TEN);

    attn2<<<dim3(ceil_div(TDE, AR), BB), 256, ATN_SMEM>>>(qenc, kenc, qsq, ksq, prior, out);
}

// round 15
// speedup vs baseline: 1.1281x; 1.1281x over previous
#include <cuda_runtime.h>
#include <cuda_bf16.h>
#include <mma.h>
#include <math.h>
#include <cstdint>

using namespace nvcuda;

#define BB   16
#define CQ   80
#define CKCH 512
#define CA   80
#define TDE  2000
#define TEN  512
#define KH1  1024
#define QH1  160
#define TEMPR 0.0005f

// ---------------- scratch ----------------
__device__ __align__(16) __nv_bfloat16 g_colk[(size_t)BB * CKCH * 3 * TEN];
__device__ __align__(16) __nv_bfloat16 g_colq[(size_t)BB * CQ   * 3 * TDE];
__device__ __align__(16) __nv_bfloat16 g_khid[(size_t)BB * KH1 * TEN];
__device__ __align__(16) __nv_bfloat16 g_qh1 [(size_t)BB * QH1 * TDE];
__device__ __align__(16) __nv_bfloat16 g_qh2 [(size_t)BB * CQ  * TDE];
__device__ __align__(16) __nv_bfloat16 g_kenc[(size_t)BB * CA  * TEN + 64];
__device__ __align__(16) __nv_bfloat16 g_qenc[(size_t)BB * CA  * TDE + 64];
__device__ __align__(16) __nv_bfloat16 g_w1k[KH1 * CKCH * 3];
__device__ __align__(16) __nv_bfloat16 g_w2k[CA * KH1];
__device__ __align__(16) __nv_bfloat16 g_w1q[QH1 * CQ * 3];
__device__ __align__(16) __nv_bfloat16 g_w2q[CA * QH1];
__device__ __align__(16) __nv_bfloat16 g_w3q[CA * CQ];
__device__ float g_ksq[BB * TEN];

// ---------------- fused weight fp32->bf16 ----------------
#define W0 393216
#define W1 20480
#define W2 9600
#define W3 3200
#define W4 1600
__global__ void wcvt(const float* a0, const float* a1, const float* a2,
                     const float* a3, const float* a4,
                     __nv_bfloat16* o0, __nv_bfloat16* o1, __nv_bfloat16* o2,
                     __nv_bfloat16* o3, __nv_bfloat16* o4)
{
    int i = blockIdx.x * blockDim.x + threadIdx.x;
    const float* src; __nv_bfloat16* dst; int j = i;
    if (j < W0)                { src = a0; dst = o0; }
    else if ((j -= W0) < W1)   { src = a1; dst = o1; }
    else if ((j -= W1) < W2)   { src = a2; dst = o2; }
    else if ((j -= W2) < W3)   { src = a3; dst = o3; }
    else if ((j -= W3) < W4)   { src = a4; dst = o4; }
    else return;
    float4 v = reinterpret_cast<const float4*>(src)[j];
    __nv_bfloat162* o = reinterpret_cast<__nv_bfloat162*>(dst) + 2 * j;
    o[0] = __floats2bfloat162_rn(v.x, v.y);
    o[1] = __floats2bfloat162_rn(v.z, v.w);
}

// ---------------- im2col (k=3, pad=1) fused with fp32->bf16 ----------------
__global__ void im2col3f(const float* __restrict__ X,
                         __nv_bfloat16* __restrict__ out, int C, int T)
{
    int b = blockIdx.y;
    int idx = blockIdx.x * blockDim.x + threadIdx.x;
    int th = T >> 1;
    int total2 = C * 3 * th;
    if (idx >= total2) return;
    int tp = idx % th;
    int row = idx / th;
    int ci = row / 3, dk = row - ci * 3;
    int t = tp * 2;
    const float* Xr = X + ((size_t)b * C + ci) * T;
    int t0 = t + dk - 1, t1 = t0 + 1;
    float v0 = (t0 >= 0 && t0 < T) ? Xr[t0] : 0.f;
    float v1 = (t1 >= 0 && t1 < T) ? Xr[t1] : 0.f;
    reinterpret_cast<__nv_bfloat162*>(out + (size_t)b * C * 3 * T + (size_t)row * T)[tp]
        = __floats2bfloat162_rn(v0, v1);
}

// ---------------- cp.async helper ----------------
__device__ __forceinline__ void cp16(uint32_t d, const void* s, bool p) {
    int sz = p ? 16 : 0;
    asm volatile("cp.async.cg.shared.global [%0], [%1], 16, %2;\n"
                 :: "r"(d), "l"(s), "r"(sz) : "memory");
}

// ---------------- conv1k GEMM: BM=128, GBK=64, 3-stage, 2 CTAs/SM ----------------
#define K128 64
#define SM128 (3 * 128 * 72 * 2 + 3 * K128 * 136 * 2)   // 107520; patch aliases As

__global__ __launch_bounds__(256, 2) void gemm128(
    const __nv_bfloat16* __restrict__ Bmat,
    const __nv_bfloat16* __restrict__ W,
    const float* __restrict__ bias,
    __nv_bfloat16* __restrict__ Y,
    int Kt, int Cout, int Nn, int do_relu)
{
    extern __shared__ char sm[];
    typedef __nv_bfloat16 bf;
    bf (*As)[128][72]  = reinterpret_cast<bf(*)[128][72]>(sm);
    bf (*Bs)[K128][136] = reinterpret_cast<bf(*)[K128][136]>(sm + 3 * 128 * 72 * 2);

    const int b  = blockIdx.z;
    const int m0 = blockIdx.y * 128;
    const int n0 = blockIdx.x * 128;
    const __nv_bfloat16* Bb = Bmat + (size_t)b * Kt * Nn;
    __nv_bfloat16*       Yb = Y    + (size_t)b * Cout * Nn;

    const int tid = threadIdx.x;
    const int warp = tid >> 5, lane = tid & 31;
    const int wm = warp >> 2, wn = warp & 3;

    wmma::fragment<wmma::accumulator, 16, 16, 16, float> acc[4][2];
#pragma unroll
    for (int i = 0; i < 4; i++)
#pragma unroll
        for (int j = 0; j < 2; j++) wmma::fill_fragment(acc[i][j], 0.f);

    const int nK = Kt / K128;

    auto load_stage = [&](int st, int k0) {
#pragma unroll
        for (int i = 0; i < 4; i++) {
            int idx = tid + 256 * i;
            int m = idx >> 3, kc = idx & 7;
            uint32_t d = (uint32_t)__cvta_generic_to_shared(&As[st][m][kc * 8]);
            cp16(d, W + (size_t)(m0 + m) * Kt + k0 + kc * 8, true);
        }
#pragma unroll
        for (int i = 0; i < 4; i++) {
            int idx = tid + 256 * i;
            int r = idx >> 4, nc = idx & 15;
            uint32_t d = (uint32_t)__cvta_generic_to_shared(&Bs[st][r][nc * 8]);
            cp16(d, Bb + (size_t)(k0 + r) * Nn + n0 + nc * 8, true);
        }
        asm volatile("cp.async.commit_group;\n" ::: "memory");
    };

    load_stage(0, 0);
    load_stage(1, K128);

    for (int kt = 0; kt < nK; kt++) {
        asm volatile("cp.async.wait_group 1;\n" ::: "memory");
        __syncthreads();
        if (kt + 2 < nK) load_stage((kt + 2) % 3, (kt + 2) * K128);
        else asm volatile("cp.async.commit_group;\n" ::: "memory");
        const int st = kt % 3;
#pragma unroll
        for (int ks = 0; ks < 4; ks++) {
            wmma::fragment<wmma::matrix_a, 16, 16, 16, __nv_bfloat16, wmma::row_major> af[4];
            wmma::fragment<wmma::matrix_b, 16, 16, 16, __nv_bfloat16, wmma::row_major> bfr[2];
#pragma unroll
            for (int i = 0; i < 4; i++)
                wmma::load_matrix_sync(af[i], &As[st][wm * 64 + i * 16][ks * 16], 72);
#pragma unroll
            for (int j = 0; j < 2; j++)
                wmma::load_matrix_sync(bfr[j], &Bs[st][ks * 16][wn * 32 + j * 16], 136);
#pragma unroll
            for (int i = 0; i < 4; i++)
#pragma unroll
                for (int j = 0; j < 2; j++)
                    wmma::mma_sync(acc[i][j], af[i], bfr[j], acc[i][j]);
        }
    }
    asm volatile("cp.async.wait_group 0;\n" ::: "memory");
    __syncthreads();

    float (*patch)[16][18] = reinterpret_cast<float(*)[16][18]>(sm);
#pragma unroll
    for (int i = 0; i < 4; i++) {
#pragma unroll
        for (int j = 0; j < 2; j++) {
            wmma::store_matrix_sync(&patch[warp][0][0], acc[i][j], 18, wmma::mem_row_major);
            __syncwarp();
            int r = lane >> 1, h = lane & 1;
            int gm = m0 + wm * 64 + i * 16 + r;
            int gn = n0 + wn * 32 + j * 16 + h * 8;
            float bv = bias[gm];
            float v[8];
#pragma unroll
            for (int e = 0; e < 8; e++) {
                float x = patch[warp][r][h * 8 + e] + bv;
                v[e] = do_relu ? fmaxf(x, 0.f) : x;
            }
            __nv_bfloat162 p[4];
            p[0] = __floats2bfloat162_rn(v[0], v[1]);
            p[1] = __floats2bfloat162_rn(v[2], v[3]);
            p[2] = __floats2bfloat162_rn(v[4], v[5]);
            p[3] = __floats2bfloat162_rn(v[6], v[7]);
            *reinterpret_cast<uint4*>(Yb + (size_t)gm * Nn + gn) =
                *reinterpret_cast<uint4*>(p);
            __syncwarp();
        }
    }
}

// ---------------- small-conv GEMM: BM=64, GBK=32, 3-stage (R10-proven) ----------------
#define GBN 128
#define GBK 32

template<int BM>
__global__ __launch_bounds__(256) void gemm_bf16(
    const __nv_bfloat16* __restrict__ Bmat,
    const __nv_bfloat16* __restrict__ W,
    const float* __restrict__ bias,
    __nv_bfloat16* __restrict__ Y,
    int Kt, int Cout, int Nn, int do_relu)
{
    extern __shared__ char sm[];
    typedef __nv_bfloat16 bf;
    bf (*As)[BM][40]  = reinterpret_cast<bf(*)[BM][40]>(sm);
    bf (*Bs)[GBK][136] = reinterpret_cast<bf(*)[GBK][136]>(sm + 3 * BM * 40 * 2);
    float (*patch)[16][18] =
        reinterpret_cast<float(*)[16][18]>(sm + 3 * BM * 40 * 2 + 3 * GBK * 136 * 2);

    const int b  = blockIdx.z;
    const int m0 = blockIdx.y * BM;
    const int n0 = blockIdx.x * GBN;
    const __nv_bfloat16* Bb = Bmat + (size_t)b * Kt * Nn;
    __nv_bfloat16*       Yb = Y    + (size_t)b * Cout * Nn;

    const int tid = threadIdx.x;
    const int warp = tid >> 5, lane = tid & 31;
    const int wm = warp >> 2, wn = warp & 3;
    constexpr int FM = BM / 32;

    wmma::fragment<wmma::accumulator, 16, 16, 16, float> acc[FM][2];
#pragma unroll
    for (int i = 0; i < FM; i++)
#pragma unroll
        for (int j = 0; j < 2; j++) wmma::fill_fragment(acc[i][j], 0.f);

    const int nK = (Kt + GBK - 1) / GBK;

    auto load_stage = [&](int st, int k0) {
#pragma unroll
        for (int idx = tid; idx < BM * 4; idx += 256) {
            int m = idx >> 2, kc = idx & 3;
            int gm = m0 + m, gk = k0 + kc * 8;
            uint32_t d = (uint32_t)__cvta_generic_to_shared(&As[st][m][kc * 8]);
            cp16(d, W + (size_t)gm * Kt + gk, (gm < Cout) && (gk < Kt));
        }
#pragma unroll
        for (int i = 0; i < 2; i++) {
            int idx = tid * 2 + i;
            int r = idx >> 4, nc = idx & 15;
            int gk = k0 + r, gn = n0 + nc * 8;
            uint32_t d = (uint32_t)__cvta_generic_to_shared(&Bs[st][r][nc * 8]);
            cp16(d, Bb + (size_t)gk * Nn + gn, (gk < Kt) && (gn < Nn));
        }
        asm volatile("cp.async.commit_group;\n" ::: "memory");
    };

    load_stage(0, 0);
    load_stage(1, GBK);

    for (int kt = 0; kt < nK; kt++) {
        asm volatile("cp.async.wait_group 1;\n" ::: "memory");
        __syncthreads();
        if (kt + 2 < nK) load_stage((kt + 2) % 3, (kt + 2) * GBK);
        else asm volatile("cp.async.commit_group;\n" ::: "memory");
        const int st = kt % 3;
#pragma unroll
        for (int ks = 0; ks < 2; ks++) {
            wmma::fragment<wmma::matrix_a, 16, 16, 16, __nv_bfloat16, wmma::row_major> af[FM];
            wmma::fragment<wmma::matrix_b, 16, 16, 16, __nv_bfloat16, wmma::row_major> bfr[2];
#pragma unroll
            for (int i = 0; i < FM; i++)
                wmma::load_matrix_sync(af[i], &As[st][wm * (BM / 2) + i * 16][ks * 16], 40);
#pragma unroll
            for (int j = 0; j < 2; j++)
                wmma::load_matrix_sync(bfr[j], &Bs[st][ks * 16][wn * 32 + j * 16], 136);
#pragma unroll
            for (int i = 0; i < FM; i++)
#pragma unroll
                for (int j = 0; j < 2; j++)
                    wmma::mma_sync(acc[i][j], af[i], bfr[j], acc[i][j]);
        }
    }

#pragma unroll
    for (int i = 0; i < FM; i++) {
#pragma unroll
        for (int j = 0; j < 2; j++) {
            wmma::store_matrix_sync(&patch[warp][0][0], acc[i][j], 18, wmma::mem_row_major);
            __syncwarp();
            int r = lane >> 1, h = lane & 1;
            int gm = m0 + wm * (BM / 2) + i * 16 + r;
            int gn = n0 + wn * 32 + j * 16 + h * 8;
            if (gm < Cout && gn < Nn) {
                float bv = bias[gm];
                float v[8];
#pragma unroll
                for (int e = 0; e < 8; e++) {
                    float x = patch[warp][r][h * 8 + e] + bv;
                    v[e] = do_relu ? fmaxf(x, 0.f) : x;
                }
                __nv_bfloat162 p[4];
                p[0] = __floats2bfloat162_rn(v[0], v[1]);
                p[1] = __floats2bfloat162_rn(v[2], v[3]);
                p[2] = __floats2bfloat162_rn(v[4], v[5]);
                p[3] = __floats2bfloat162_rn(v[6], v[7]);
                *reinterpret_cast<uint4*>(Yb + (size_t)gm * Nn + gn) =
                    *reinterpret_cast<uint4*>(p);
            }
            __syncwarp();
        }
    }
}

// ---------------- squared channel norms (keys only; scalar R10 form) ----------------
__global__ void sqnorm_bf16(const __nv_bfloat16* __restrict__ X,
                            float* __restrict__ out, int C, int T)
{
    int b = blockIdx.y;
    int t = blockIdx.x * blockDim.x + threadIdx.x;
    if (t >= T) return;
    const __nv_bfloat16* Xb = X + (size_t)b * C * T + t;
    float s = 0.f;
    for (int c = 0; c < C; c++) {
        float v = __bfloat162float(Xb[(size_t)c * T]);
        s += v * v;
    }
    out[b * T + t] = s;
}

// ---------------- attn: wmma QK (B from L2) + R10 dual softmax, qsq fused in ----------------
#define AR 32
#define ATN_SMEM (6400 + 2048 + 66048)   // qs + ksq + lg = 74496

__global__ __launch_bounds__(256) void attn2(
    const __nv_bfloat16* __restrict__ qenc, const __nv_bfloat16* __restrict__ kenc,
    const float* __restrict__ ksq,
    const float* __restrict__ prior, float* __restrict__ out)
{
    extern __shared__ char sm[];
    typedef __nv_bfloat16 bf;
    bf (*qs)[40]    = reinterpret_cast<bf(*)[40]>(sm);
    float* ksq_s    = reinterpret_cast<float*>(sm + 6400);
    float (*lg)[516]= reinterpret_cast<float(*)[516]>(sm + 6400 + 2048);

    const int b  = blockIdx.y;
    const int t0 = blockIdx.x * AR;
    const int tid = threadIdx.x;
    const int warp = tid >> 5;

    const bf* kb = kenc + (size_t)b * CA * TEN;
    const bf* qb = qenc + (size_t)b * CA * TDE;

#pragma unroll
    for (int i = 0; i < 10; i++) {
        int idx = tid + 256 * i;
        int ch = idx >> 5, j = idx & 31;
        qs[ch][j] = qb[(size_t)ch * TDE + t0 + j];
    }
    for (int i = tid; i < TEN; i += 256) ksq_s[i] = ksq[b * TEN + i];
    __syncthreads();

    {
        wmma::fragment<wmma::accumulator, 16, 16, 16, float> acc[2][4];
#pragma unroll
        for (int i = 0; i < 2; i++)
#pragma unroll
            for (int j = 0; j < 4; j++) wmma::fill_fragment(acc[i][j], 0.f);
#pragma unroll
        for (int ks = 0; ks < 5; ks++) {
            wmma::fragment<wmma::matrix_a, 16, 16, 16, bf, wmma::col_major> af[2];
            wmma::fragment<wmma::matrix_b, 16, 16, 16, bf, wmma::row_major> bfr[4];
#pragma unroll
            for (int i = 0; i < 2; i++)
                wmma::load_matrix_sync(af[i], &qs[ks * 16][i * 16], 40);
#pragma unroll
            for (int j = 0; j < 4; j++)
                wmma::load_matrix_sync(bfr[j],
                    kb + (size_t)(ks * 16) * TEN + warp * 64 + j * 16, TEN);
#pragma unroll
            for (int i = 0; i < 2; i++)
#pragma unroll
                for (int j = 0; j < 4; j++)
                    wmma::mma_sync(acc[i][j], af[i], bfr[j], acc[i][j]);
        }
#pragma unroll
        for (int i = 0; i < 2; i++)
#pragma unroll
            for (int j = 0; j < 4; j++)
                wmma::store_matrix_sync(&lg[i * 16][warp * 64 + j * 16], acc[i][j],
                                        516, wmma::mem_row_major);
    }
    __syncthreads();

    // R10-proven softmax structure; qsq computed in-block from the staged q tile.
    const int r = tid >> 3, c = tid & 7;
    const int gr = t0 + r;
    const bool valid = gr < TDE;
    float4* lgr = reinterpret_cast<float4*>(&lg[r][0]);
    const float4* ksq4 = reinterpret_cast<const float4*>(ksq_s);

    // qsq_r = sum_ch q[ch][r]^2 : 10 channels per lane, reduce over the 8-lane group
    float qsq_r = 0.f;
#pragma unroll
    for (int k = 0; k < 10; k++) {
        float v = __bfloat162float(qs[c + 8 * k][r]);
        qsq_r += v * v;
    }
#pragma unroll
    for (int msk = 4; msk >= 1; msk >>= 1)
        qsq_r += __shfl_xor_sync(0xffffffffu, qsq_r, msk);

    float m1 = -INFINITY;
#pragma unroll
    for (int u = 0; u < 16; u++) {
        int i4 = c + 8 * u;
        float4 v = lgr[i4];
        float4 k4 = ksq4[i4];
        v.x = TEMPR * (2.f * v.x - qsq_r - k4.x);
        v.y = TEMPR * (2.f * v.y - qsq_r - k4.y);
        v.z = TEMPR * (2.f * v.z - qsq_r - k4.z);
        v.w = TEMPR * (2.f * v.w - qsq_r - k4.w);
        lgr[i4] = v;
        m1 = fmaxf(m1, fmaxf(fmaxf(v.x, v.y), fmaxf(v.z, v.w)));
    }
#pragma unroll
    for (int msk = 4; msk >= 1; msk >>= 1)
        m1 = fmaxf(m1, __shfl_xor_sync(0xffffffffu, m1, msk));
    float s1 = 0.f;
#pragma unroll
    for (int u = 0; u < 16; u++) {
        float4 v = lgr[c + 8 * u];
        s1 += __expf(v.x - m1) + __expf(v.y - m1) + __expf(v.z - m1) + __expf(v.w - m1);
    }
#pragma unroll
    for (int msk = 4; msk >= 1; msk >>= 1)
        s1 += __shfl_xor_sync(0xffffffffu, s1, msk);
    const float logZ = m1 + __logf(s1);

    const size_t row = ((size_t)b * TDE + gr) * TEN;
    const size_t NT = (size_t)BB * TDE * TEN;
    const float4* pr4 = reinterpret_cast<const float4*>(prior + row);
    float4* olp = reinterpret_cast<float4*>(out + NT + row);
    float m2 = -INFINITY;
#pragma unroll
    for (int u = 0; u < 16; u++) {
        int i4 = c + 8 * u;
        float4 v = lgr[i4];
        if (valid) {
            float4 p = pr4[i4];
            v.x = v.x - logZ + __logf(p.x + 1e-8f);
            v.y = v.y - logZ + __logf(p.y + 1e-8f);
            v.z = v.z - logZ + __logf(p.z + 1e-8f);
            v.w = v.w - logZ + __logf(p.w + 1e-8f);
            olp[i4] = v;
            lgr[i4] = v;
        }
        m2 = fmaxf(m2, fmaxf(fmaxf(v.x, v.y), fmaxf(v.z, v.w)));
    }
#pragma unroll
    for (int msk = 4; msk >= 1; msk >>= 1)
        m2 = fmaxf(m2, __shfl_xor_sync(0xffffffffu, m2, msk));
    float s2 = 0.f;
#pragma unroll
    for (int u = 0; u < 16; u++) {
        int i4 = c + 8 * u;
        float4 v = lgr[i4];
        v.x = __expf(v.x - m2); v.y = __expf(v.y - m2);
        v.z = __expf(v.z - m2); v.w = __expf(v.w - m2);
        lgr[i4] = v;
        s2 += v.x + v.y + v.z + v.w;
    }
#pragma unroll
    for (int msk = 4; msk >= 1; msk >>= 1)
        s2 += __shfl_xor_sync(0xffffffffu, s2, msk);
    const float inv = 1.f / s2;
    float4* oat = reinterpret_cast<float4*>(out + row);
    if (valid) {
#pragma unroll
        for (int u = 0; u < 16; u++) {
            int i4 = c + 8 * u;
            float4 v = lgr[i4];
            float4 w = { v.x * inv, v.y * inv, v.z * inv, v.w * inv };
            oat[i4] = w;
        }
    }
}

// ---------------- launch ----------------
static inline int ceil_div(int a, int b) { return (a + b - 1) / b; }

extern "C" void kernel_launch(void* const* d_in, const int* in_sizes, int n_in,
                              void* d_out, int out_size)
{
    const float* queries = (const float*)d_in[0];
    const float* keys    = (const float*)d_in[1];
    const float* prior   = (const float*)d_in[3];
    const float* kp_w1 = (const float*)d_in[4];
    const float* kp_b1 = (const float*)d_in[5];
    const float* kp_w2 = (const float*)d_in[6];
    const float* kp_b2 = (const float*)d_in[7];
    const float* qp_w1 = (const float*)d_in[8];
    const float* qp_b1 = (const float*)d_in[9];
    const float* qp_w2 = (const float*)d_in[10];
    const float* qp_b2 = (const float*)d_in[11];
    const float* qp_w3 = (const float*)d_in[12];
    const float* qp_b3 = (const float*)d_in[13];
    float* out = (float*)d_out;

    __nv_bfloat16 *colk, *colq, *khid, *qh1, *qh2, *kenc, *qenc;
    __nv_bfloat16 *w1k, *w2k, *w1q, *w2q, *w3q;
    float *ksq;
    cudaGetSymbolAddress((void**)&colk, g_colk);
    cudaGetSymbolAddress((void**)&colq, g_colq);
    cudaGetSymbolAddress((void**)&khid, g_khid);
    cudaGetSymbolAddress((void**)&qh1,  g_qh1);
    cudaGetSymbolAddress((void**)&qh2,  g_qh2);
    cudaGetSymbolAddress((void**)&kenc, g_kenc);
    cudaGetSymbolAddress((void**)&qenc, g_qenc);
    cudaGetSymbolAddress((void**)&w1k,  g_w1k);
    cudaGetSymbolAddress((void**)&w2k,  g_w2k);
    cudaGetSymbolAddress((void**)&w1q,  g_w1q);
    cudaGetSymbolAddress((void**)&w2q,  g_w2q);
    cudaGetSymbolAddress((void**)&w3q,  g_w3q);
    cudaGetSymbolAddress((void**)&ksq,  g_ksq);

    const int SM64 = 3 * 64 * 40 * 2 + 3 * GBK * 136 * 2 + 8 * 16 * 18 * 4; // 50688
    cudaFuncSetAttribute(gemm128, cudaFuncAttributeMaxDynamicSharedMemorySize, SM128);
    cudaFuncSetAttribute(gemm_bf16<64>, cudaFuncAttributeMaxDynamicSharedMemorySize, SM64);
    cudaFuncSetAttribute(attn2, cudaFuncAttributeMaxDynamicSharedMemorySize, ATN_SMEM);

    // weights -> bf16 (single launch)
    wcvt<<<ceil_div(W0 + W1 + W2 + W3 + W4, 256), 256>>>(
        kp_w1, kp_w2, qp_w1, qp_w2, qp_w3, w1k, w2k, w1q, w2q, w3q);

    // fused im2col + cvt
    im2col3f<<<dim3(ceil_div(CKCH * 3 * TEN / 2, 256), BB), 256>>>(keys, colk, CKCH, TEN);
    im2col3f<<<dim3(ceil_div(CQ * 3 * TDE / 2, 256), BB), 256>>>(queries, colq, CQ, TDE);

    // conv1k: BM=128 GBK=64, 2 CTAs/SM
    gemm128<<<dim3(TEN / 128, KH1 / 128, BB), 256, SM128>>>(
        colk, w1k, kp_b1, khid, CKCH * 3, KH1, TEN, 1);

    // small convs: BM=64 (R10-proven)
    gemm_bf16<64><<<dim3(ceil_div(TEN, GBN), ceil_div(CA, 64), BB), 256, SM64>>>(
        khid, w2k, kp_b2, kenc, KH1, CA, TEN, 0);
    gemm_bf16<64><<<dim3(ceil_div(TDE, GBN), ceil_div(QH1, 64), BB), 256, SM64>>>(
        colq, w1q, qp_b1, qh1, CQ * 3, QH1, TDE, 1);
    gemm_bf16<64><<<dim3(ceil_div(TDE, GBN), ceil_div(CA, 64), BB), 256, SM64>>>(
        qh1, w2q, qp_b2, qh2, QH1, CA, TDE, 1);
    gemm_bf16<64><<<dim3(ceil_div(TDE, GBN), ceil_div(CA, 64), BB), 256, SM64>>>(
        qh2, w3q, qp_b3, qenc, CQ, CA, TDE, 0);

    // ksq only (qsq fused into attn2)
    sqnorm_bf16<<<dim3(ceil_div(TEN, 256), BB), 256>>>(kenc, ksq, CA, TEN);

    attn2<<<dim3(ceil_div(TDE, AR), BB), 256, ATN_SMEM>>>(qenc, kenc, ksq, prior, out);
}

// round 16
// speedup vs baseline: 1.2252x; 1.0861x over previous
#include <cuda_runtime.h>
#include <cuda_bf16.h>
#include <mma.h>
#include <math.h>
#include <cstdint>

using namespace nvcuda;

#define BB   16
#define CQ   80
#define CKCH 512
#define CA   80
#define TDE  2000
#define TEN  512
#define KH1  1024
#define QH1  160
#define TEMPR 0.0005f

// ---------------- scratch ----------------
__device__ __align__(16) __nv_bfloat16 g_colk[(size_t)BB * CKCH * 3 * TEN];
__device__ __align__(16) __nv_bfloat16 g_colq[(size_t)BB * CQ   * 3 * TDE];
__device__ __align__(16) __nv_bfloat16 g_khid[(size_t)BB * KH1 * TEN];
__device__ __align__(16) __nv_bfloat16 g_qh1 [(size_t)BB * QH1 * TDE];
__device__ __align__(16) __nv_bfloat16 g_qh2 [(size_t)BB * CQ  * TDE];
__device__ __align__(16) __nv_bfloat16 g_kenc[(size_t)BB * CA  * TEN + 64];
__device__ __align__(16) __nv_bfloat16 g_qenc[(size_t)BB * CA  * TDE + 64];
__device__ __align__(16) __nv_bfloat16 g_w1k[KH1 * CKCH * 3];
__device__ __align__(16) __nv_bfloat16 g_w2k[CA * KH1];
__device__ __align__(16) __nv_bfloat16 g_w1q[QH1 * CQ * 3];
__device__ __align__(16) __nv_bfloat16 g_w2q[CA * QH1];
__device__ __align__(16) __nv_bfloat16 g_w3q[CA * CQ];
__device__ float g_ksq[BB * TEN];

// ---------------- fused weight fp32->bf16 ----------------
#define W0 393216
#define W1 20480
#define W2 9600
#define W3 3200
#define W4 1600
__global__ void wcvt(const float* a0, const float* a1, const float* a2,
                     const float* a3, const float* a4,
                     __nv_bfloat16* o0, __nv_bfloat16* o1, __nv_bfloat16* o2,
                     __nv_bfloat16* o3, __nv_bfloat16* o4)
{
    int i = blockIdx.x * blockDim.x + threadIdx.x;
    const float* src; __nv_bfloat16* dst; int j = i;
    if (j < W0)                { src = a0; dst = o0; }
    else if ((j -= W0) < W1)   { src = a1; dst = o1; }
    else if ((j -= W1) < W2)   { src = a2; dst = o2; }
    else if ((j -= W2) < W3)   { src = a3; dst = o3; }
    else if ((j -= W3) < W4)   { src = a4; dst = o4; }
    else return;
    float4 v = reinterpret_cast<const float4*>(src)[j];
    __nv_bfloat162* o = reinterpret_cast<__nv_bfloat162*>(dst) + 2 * j;
    o[0] = __floats2bfloat162_rn(v.x, v.y);
    o[1] = __floats2bfloat162_rn(v.z, v.w);
}

// ---------------- im2col (k=3, pad=1) fused with fp32->bf16 ----------------
__global__ void im2col3f(const float* __restrict__ X,
                         __nv_bfloat16* __restrict__ out, int C, int T)
{
    int b = blockIdx.y;
    int idx = blockIdx.x * blockDim.x + threadIdx.x;
    int th = T >> 1;
    int total2 = C * 3 * th;
    if (idx >= total2) return;
    int tp = idx % th;
    int row = idx / th;
    int ci = row / 3, dk = row - ci * 3;
    int t = tp * 2;
    const float* Xr = X + ((size_t)b * C + ci) * T;
    int t0 = t + dk - 1, t1 = t0 + 1;
    float v0 = (t0 >= 0 && t0 < T) ? Xr[t0] : 0.f;
    float v1 = (t1 >= 0 && t1 < T) ? Xr[t1] : 0.f;
    reinterpret_cast<__nv_bfloat162*>(out + (size_t)b * C * 3 * T + (size_t)row * T)[tp]
        = __floats2bfloat162_rn(v0, v1);
}

// ---------------- cp.async helper ----------------
__device__ __forceinline__ void cp16(uint32_t d, const void* s, bool p) {
    int sz = p ? 16 : 0;
    asm volatile("cp.async.cg.shared.global [%0], [%1], 16, %2;\n"
                 :: "r"(d), "l"(s), "r"(sz) : "memory");
}

// ---------------- conv1k GEMM: BM=128, GBK=64, 3-stage, 2 CTAs/SM ----------------
#define K128 64
#define SM128 (3 * 128 * 72 * 2 + 3 * K128 * 136 * 2)   // 107520; patch aliases As

__global__ __launch_bounds__(256, 2) void gemm128(
    const __nv_bfloat16* __restrict__ Bmat,
    const __nv_bfloat16* __restrict__ W,
    const float* __restrict__ bias,
    __nv_bfloat16* __restrict__ Y,
    int Kt, int Cout, int Nn, int do_relu)
{
    extern __shared__ char sm[];
    typedef __nv_bfloat16 bf;
    bf (*As)[128][72]  = reinterpret_cast<bf(*)[128][72]>(sm);
    bf (*Bs)[K128][136] = reinterpret_cast<bf(*)[K128][136]>(sm + 3 * 128 * 72 * 2);

    const int b  = blockIdx.z;
    const int m0 = blockIdx.y * 128;
    const int n0 = blockIdx.x * 128;
    const __nv_bfloat16* Bb = Bmat + (size_t)b * Kt * Nn;
    __nv_bfloat16*       Yb = Y    + (size_t)b * Cout * Nn;

    const int tid = threadIdx.x;
    const int warp = tid >> 5, lane = tid & 31;
    const int wm = warp >> 2, wn = warp & 3;

    wmma::fragment<wmma::accumulator, 16, 16, 16, float> acc[4][2];
#pragma unroll
    for (int i = 0; i < 4; i++)
#pragma unroll
        for (int j = 0; j < 2; j++) wmma::fill_fragment(acc[i][j], 0.f);

    const int nK = Kt / K128;

    auto load_stage = [&](int st, int k0) {
#pragma unroll
        for (int i = 0; i < 4; i++) {
            int idx = tid + 256 * i;
            int m = idx >> 3, kc = idx & 7;
            uint32_t d = (uint32_t)__cvta_generic_to_shared(&As[st][m][kc * 8]);
            cp16(d, W + (size_t)(m0 + m) * Kt + k0 + kc * 8, true);
        }
#pragma unroll
        for (int i = 0; i < 4; i++) {
            int idx = tid + 256 * i;
            int r = idx >> 4, nc = idx & 15;
            uint32_t d = (uint32_t)__cvta_generic_to_shared(&Bs[st][r][nc * 8]);
            cp16(d, Bb + (size_t)(k0 + r) * Nn + n0 + nc * 8, true);
        }
        asm volatile("cp.async.commit_group;\n" ::: "memory");
    };

    load_stage(0, 0);
    load_stage(1, K128);

    for (int kt = 0; kt < nK; kt++) {
        asm volatile("cp.async.wait_group 1;\n" ::: "memory");
        __syncthreads();
        if (kt + 2 < nK) load_stage((kt + 2) % 3, (kt + 2) * K128);
        else asm volatile("cp.async.commit_group;\n" ::: "memory");
        const int st = kt % 3;
#pragma unroll
        for (int ks = 0; ks < 4; ks++) {
            wmma::fragment<wmma::matrix_a, 16, 16, 16, __nv_bfloat16, wmma::row_major> af[4];
            wmma::fragment<wmma::matrix_b, 16, 16, 16, __nv_bfloat16, wmma::row_major> bfr[2];
#pragma unroll
            for (int i = 0; i < 4; i++)
                wmma::load_matrix_sync(af[i], &As[st][wm * 64 + i * 16][ks * 16], 72);
#pragma unroll
            for (int j = 0; j < 2; j++)
                wmma::load_matrix_sync(bfr[j], &Bs[st][ks * 16][wn * 32 + j * 16], 136);
#pragma unroll
            for (int i = 0; i < 4; i++)
#pragma unroll
                for (int j = 0; j < 2; j++)
                    wmma::mma_sync(acc[i][j], af[i], bfr[j], acc[i][j]);
        }
    }
    asm volatile("cp.async.wait_group 0;\n" ::: "memory");
    __syncthreads();

    float (*patch)[16][18] = reinterpret_cast<float(*)[16][18]>(sm);
#pragma unroll
    for (int i = 0; i < 4; i++) {
#pragma unroll
        for (int j = 0; j < 2; j++) {
            wmma::store_matrix_sync(&patch[warp][0][0], acc[i][j], 18, wmma::mem_row_major);
            __syncwarp();
            int r = lane >> 1, h = lane & 1;
            int gm = m0 + wm * 64 + i * 16 + r;
            int gn = n0 + wn * 32 + j * 16 + h * 8;
            float bv = bias[gm];
            float v[8];
#pragma unroll
            for (int e = 0; e < 8; e++) {
                float x = patch[warp][r][h * 8 + e] + bv;
                v[e] = do_relu ? fmaxf(x, 0.f) : x;
            }
            __nv_bfloat162 p[4];
            p[0] = __floats2bfloat162_rn(v[0], v[1]);
            p[1] = __floats2bfloat162_rn(v[2], v[3]);
            p[2] = __floats2bfloat162_rn(v[4], v[5]);
            p[3] = __floats2bfloat162_rn(v[6], v[7]);
            *reinterpret_cast<uint4*>(Yb + (size_t)gm * Nn + gn) =
                *reinterpret_cast<uint4*>(p);
            __syncwarp();
        }
    }
}

// ---------------- small-conv GEMM: BM=64, GBK=32, 3-stage (R10-proven) ----------------
#define GBN 128
#define GBK 32

template<int BM>
__global__ __launch_bounds__(256) void gemm_bf16(
    const __nv_bfloat16* __restrict__ Bmat,
    const __nv_bfloat16* __restrict__ W,
    const float* __restrict__ bias,
    __nv_bfloat16* __restrict__ Y,
    int Kt, int Cout, int Nn, int do_relu)
{
    extern __shared__ char sm[];
    typedef __nv_bfloat16 bf;
    bf (*As)[BM][40]  = reinterpret_cast<bf(*)[BM][40]>(sm);
    bf (*Bs)[GBK][136] = reinterpret_cast<bf(*)[GBK][136]>(sm + 3 * BM * 40 * 2);
    float (*patch)[16][18] =
        reinterpret_cast<float(*)[16][18]>(sm + 3 * BM * 40 * 2 + 3 * GBK * 136 * 2);

    const int b  = blockIdx.z;
    const int m0 = blockIdx.y * BM;
    const int n0 = blockIdx.x * GBN;
    const __nv_bfloat16* Bb = Bmat + (size_t)b * Kt * Nn;
    __nv_bfloat16*       Yb = Y    + (size_t)b * Cout * Nn;

    const int tid = threadIdx.x;
    const int warp = tid >> 5, lane = tid & 31;
    const int wm = warp >> 2, wn = warp & 3;
    constexpr int FM = BM / 32;

    wmma::fragment<wmma::accumulator, 16, 16, 16, float> acc[FM][2];
#pragma unroll
    for (int i = 0; i < FM; i++)
#pragma unroll
        for (int j = 0; j < 2; j++) wmma::fill_fragment(acc[i][j], 0.f);

    const int nK = (Kt + GBK - 1) / GBK;

    auto load_stage = [&](int st, int k0) {
#pragma unroll
        for (int idx = tid; idx < BM * 4; idx += 256) {
            int m = idx >> 2, kc = idx & 3;
            int gm = m0 + m, gk = k0 + kc * 8;
            uint32_t d = (uint32_t)__cvta_generic_to_shared(&As[st][m][kc * 8]);
            cp16(d, W + (size_t)gm * Kt + gk, (gm < Cout) && (gk < Kt));
        }
#pragma unroll
        for (int i = 0; i < 2; i++) {
            int idx = tid * 2 + i;
            int r = idx >> 4, nc = idx & 15;
            int gk = k0 + r, gn = n0 + nc * 8;
            uint32_t d = (uint32_t)__cvta_generic_to_shared(&Bs[st][r][nc * 8]);
            cp16(d, Bb + (size_t)gk * Nn + gn, (gk < Kt) && (gn < Nn));
        }
        asm volatile("cp.async.commit_group;\n" ::: "memory");
    };

    load_stage(0, 0);
    load_stage(1, GBK);

    for (int kt = 0; kt < nK; kt++) {
        asm volatile("cp.async.wait_group 1;\n" ::: "memory");
        __syncthreads();
        if (kt + 2 < nK) load_stage((kt + 2) % 3, (kt + 2) * GBK);
        else asm volatile("cp.async.commit_group;\n" ::: "memory");
        const int st = kt % 3;
#pragma unroll
        for (int ks = 0; ks < 2; ks++) {
            wmma::fragment<wmma::matrix_a, 16, 16, 16, __nv_bfloat16, wmma::row_major> af[FM];
            wmma::fragment<wmma::matrix_b, 16, 16, 16, __nv_bfloat16, wmma::row_major> bfr[2];
#pragma unroll
            for (int i = 0; i < FM; i++)
                wmma::load_matrix_sync(af[i], &As[st][wm * (BM / 2) + i * 16][ks * 16], 40);
#pragma unroll
            for (int j = 0; j < 2; j++)
                wmma::load_matrix_sync(bfr[j], &Bs[st][ks * 16][wn * 32 + j * 16], 136);
#pragma unroll
            for (int i = 0; i < FM; i++)
#pragma unroll
                for (int j = 0; j < 2; j++)
                    wmma::mma_sync(acc[i][j], af[i], bfr[j], acc[i][j]);
        }
    }

#pragma unroll
    for (int i = 0; i < FM; i++) {
#pragma unroll
        for (int j = 0; j < 2; j++) {
            wmma::store_matrix_sync(&patch[warp][0][0], acc[i][j], 18, wmma::mem_row_major);
            __syncwarp();
            int r = lane >> 1, h = lane & 1;
            int gm = m0 + wm * (BM / 2) + i * 16 + r;
            int gn = n0 + wn * 32 + j * 16 + h * 8;
            if (gm < Cout && gn < Nn) {
                float bv = bias[gm];
                float v[8];
#pragma unroll
                for (int e = 0; e < 8; e++) {
                    float x = patch[warp][r][h * 8 + e] + bv;
                    v[e] = do_relu ? fmaxf(x, 0.f) : x;
                }
                __nv_bfloat162 p[4];
                p[0] = __floats2bfloat162_rn(v[0], v[1]);
                p[1] = __floats2bfloat162_rn(v[2], v[3]);
                p[2] = __floats2bfloat162_rn(v[4], v[5]);
                p[3] = __floats2bfloat162_rn(v[6], v[7]);
                *reinterpret_cast<uint4*>(Yb + (size_t)gm * Nn + gn) =
                    *reinterpret_cast<uint4*>(p);
            }
            __syncwarp();
        }
    }
}

// ---------------- squared channel norms (keys only; scalar R10 form) ----------------
__global__ void sqnorm_bf16(const __nv_bfloat16* __restrict__ X,
                            float* __restrict__ out, int C, int T)
{
    int b = blockIdx.y;
    int t = blockIdx.x * blockDim.x + threadIdx.x;
    if (t >= T) return;
    const __nv_bfloat16* Xb = X + (size_t)b * C * T + t;
    float s = 0.f;
    for (int c = 0; c < C; c++) {
        float v = __bfloat162float(Xb[(size_t)c * T]);
        s += v * v;
    }
    out[b * T + t] = s;
}

// ---------------- attn: wmma QK (B from L2) + R10 dual softmax, qsq fused in ----------------
#define AR 32
#define ATN_SMEM (6400 + 2048 + 66048)   // qs + ksq + lg = 74496

__global__ __launch_bounds__(256) void attn2(
    const __nv_bfloat16* __restrict__ qenc, const __nv_bfloat16* __restrict__ kenc,
    const float* __restrict__ ksq,
    const float* __restrict__ prior, float* __restrict__ out)
{
    extern __shared__ char sm[];
    typedef __nv_bfloat16 bf;
    bf (*qs)[40]    = reinterpret_cast<bf(*)[40]>(sm);
    float* ksq_s    = reinterpret_cast<float*>(sm + 6400);
    float (*lg)[516]= reinterpret_cast<float(*)[516]>(sm + 6400 + 2048);

    const int b  = blockIdx.y;
    const int t0 = blockIdx.x * AR;
    const int tid = threadIdx.x;
    const int warp = tid >> 5;

    const bf* kb = kenc + (size_t)b * CA * TEN;
    const bf* qb = qenc + (size_t)b * CA * TDE;

#pragma unroll
    for (int i = 0; i < 10; i++) {
        int idx = tid + 256 * i;
        int ch = idx >> 5, j = idx & 31;
        qs[ch][j] = qb[(size_t)ch * TDE + t0 + j];
    }
    for (int i = tid; i < TEN; i += 256) ksq_s[i] = ksq[b * TEN + i];
    __syncthreads();

    {
        wmma::fragment<wmma::accumulator, 16, 16, 16, float> acc[2][4];
#pragma unroll
        for (int i = 0; i < 2; i++)
#pragma unroll
            for (int j = 0; j < 4; j++) wmma::fill_fragment(acc[i][j], 0.f);
#pragma unroll
        for (int ks = 0; ks < 5; ks++) {
            wmma::fragment<wmma::matrix_a, 16, 16, 16, bf, wmma::col_major> af[2];
            wmma::fragment<wmma::matrix_b, 16, 16, 16, bf, wmma::row_major> bfr[4];
#pragma unroll
            for (int i = 0; i < 2; i++)
                wmma::load_matrix_sync(af[i], &qs[ks * 16][i * 16], 40);
#pragma unroll
            for (int j = 0; j < 4; j++)
                wmma::load_matrix_sync(bfr[j],
                    kb + (size_t)(ks * 16) * TEN + warp * 64 + j * 16, TEN);
#pragma unroll
            for (int i = 0; i < 2; i++)
#pragma unroll
                for (int j = 0; j < 4; j++)
                    wmma::mma_sync(acc[i][j], af[i], bfr[j], acc[i][j]);
        }
#pragma unroll
        for (int i = 0; i < 2; i++)
#pragma unroll
            for (int j = 0; j < 4; j++)
                wmma::store_matrix_sync(&lg[i * 16][warp * 64 + j * 16], acc[i][j],
                                        516, wmma::mem_row_major);
    }
    __syncthreads();

    const int r = tid >> 3, c = tid & 7;
    const int gr = t0 + r;
    const bool valid = gr < TDE;
    float4* lgr = reinterpret_cast<float4*>(&lg[r][0]);
    const float4* ksq4 = reinterpret_cast<const float4*>(ksq_s);

    float qsq_r = 0.f;
#pragma unroll
    for (int k = 0; k < 10; k++) {
        float v = __bfloat162float(qs[c + 8 * k][r]);
        qsq_r += v * v;
    }
#pragma unroll
    for (int msk = 4; msk >= 1; msk >>= 1)
        qsq_r += __shfl_xor_sync(0xffffffffu, qsq_r, msk);

    float m1 = -INFINITY;
#pragma unroll
    for (int u = 0; u < 16; u++) {
        int i4 = c + 8 * u;
        float4 v = lgr[i4];
        float4 k4 = ksq4[i4];
        v.x = TEMPR * (2.f * v.x - qsq_r - k4.x);
        v.y = TEMPR * (2.f * v.y - qsq_r - k4.y);
        v.z = TEMPR * (2.f * v.z - qsq_r - k4.z);
        v.w = TEMPR * (2.f * v.w - qsq_r - k4.w);
        lgr[i4] = v;
        m1 = fmaxf(m1, fmaxf(fmaxf(v.x, v.y), fmaxf(v.z, v.w)));
    }
#pragma unroll
    for (int msk = 4; msk >= 1; msk >>= 1)
        m1 = fmaxf(m1, __shfl_xor_sync(0xffffffffu, m1, msk));
    float s1 = 0.f;
#pragma unroll
    for (int u = 0; u < 16; u++) {
        float4 v = lgr[c + 8 * u];
        s1 += __expf(v.x - m1) + __expf(v.y - m1) + __expf(v.z - m1) + __expf(v.w - m1);
    }
#pragma unroll
    for (int msk = 4; msk >= 1; msk >>= 1)
        s1 += __shfl_xor_sync(0xffffffffu, s1, msk);
    const float logZ = m1 + __logf(s1);

    const size_t row = ((size_t)b * TDE + gr) * TEN;
    const size_t NT = (size_t)BB * TDE * TEN;
    const float4* pr4 = reinterpret_cast<const float4*>(prior + row);
    float4* olp = reinterpret_cast<float4*>(out + NT + row);
    float m2 = -INFINITY;
#pragma unroll
    for (int u = 0; u < 16; u++) {
        int i4 = c + 8 * u;
        float4 v = lgr[i4];
        if (valid) {
            float4 p = pr4[i4];
            v.x = v.x - logZ + __logf(p.x + 1e-8f);
            v.y = v.y - logZ + __logf(p.y + 1e-8f);
            v.z = v.z - logZ + __logf(p.z + 1e-8f);
            v.w = v.w - logZ + __logf(p.w + 1e-8f);
            olp[i4] = v;
            lgr[i4] = v;
        }
        m2 = fmaxf(m2, fmaxf(fmaxf(v.x, v.y), fmaxf(v.z, v.w)));
    }
#pragma unroll
    for (int msk = 4; msk >= 1; msk >>= 1)
        m2 = fmaxf(m2, __shfl_xor_sync(0xffffffffu, m2, msk));
    float s2 = 0.f;
#pragma unroll
    for (int u = 0; u < 16; u++) {
        int i4 = c + 8 * u;
        float4 v = lgr[i4];
        v.x = __expf(v.x - m2); v.y = __expf(v.y - m2);
        v.z = __expf(v.z - m2); v.w = __expf(v.w - m2);
        lgr[i4] = v;
        s2 += v.x + v.y + v.z + v.w;
    }
#pragma unroll
    for (int msk = 4; msk >= 1; msk >>= 1)
        s2 += __shfl_xor_sync(0xffffffffu, s2, msk);
    const float inv = 1.f / s2;
    float4* oat = reinterpret_cast<float4*>(out + row);
    if (valid) {
#pragma unroll
        for (int u = 0; u < 16; u++) {
            int i4 = c + 8 * u;
            float4 v = lgr[i4];
            float4 w = { v.x * inv, v.y * inv, v.z * inv, v.w * inv };
            oat[i4] = w;
        }
    }
}

// ---------------- launch ----------------
static inline int ceil_div(int a, int b) { return (a + b - 1) / b; }

extern "C" void kernel_launch(void* const* d_in, const int* in_sizes, int n_in,
                              void* d_out, int out_size)
{
    const float* queries = (const float*)d_in[0];
    const float* keys    = (const float*)d_in[1];
    const float* prior   = (const float*)d_in[3];
    const float* kp_w1 = (const float*)d_in[4];
    const float* kp_b1 = (const float*)d_in[5];
    const float* kp_w2 = (const float*)d_in[6];
    const float* kp_b2 = (const float*)d_in[7];
    const float* qp_w1 = (const float*)d_in[8];
    const float* qp_b1 = (const float*)d_in[9];
    const float* qp_w2 = (const float*)d_in[10];
    const float* qp_b2 = (const float*)d_in[11];
    const float* qp_w3 = (const float*)d_in[12];
    const float* qp_b3 = (const float*)d_in[13];
    float* out = (float*)d_out;

    __nv_bfloat16 *colk, *colq, *khid, *qh1, *qh2, *kenc, *qenc;
    __nv_bfloat16 *w1k, *w2k, *w1q, *w2q, *w3q;
    float *ksq;
    cudaGetSymbolAddress((void**)&colk, g_colk);
    cudaGetSymbolAddress((void**)&colq, g_colq);
    cudaGetSymbolAddress((void**)&khid, g_khid);
    cudaGetSymbolAddress((void**)&qh1,  g_qh1);
    cudaGetSymbolAddress((void**)&qh2,  g_qh2);
    cudaGetSymbolAddress((void**)&kenc, g_kenc);
    cudaGetSymbolAddress((void**)&qenc, g_qenc);
    cudaGetSymbolAddress((void**)&w1k,  g_w1k);
    cudaGetSymbolAddress((void**)&w2k,  g_w2k);
    cudaGetSymbolAddress((void**)&w1q,  g_w1q);
    cudaGetSymbolAddress((void**)&w2q,  g_w2q);
    cudaGetSymbolAddress((void**)&w3q,  g_w3q);
    cudaGetSymbolAddress((void**)&ksq,  g_ksq);

    const int SM64 = 3 * 64 * 40 * 2 + 3 * GBK * 136 * 2 + 8 * 16 * 18 * 4; // 50688
    cudaFuncSetAttribute(gemm128, cudaFuncAttributeMaxDynamicSharedMemorySize, SM128);
    cudaFuncSetAttribute(gemm_bf16<64>, cudaFuncAttributeMaxDynamicSharedMemorySize, SM64);
    cudaFuncSetAttribute(attn2, cudaFuncAttributeMaxDynamicSharedMemorySize, ATN_SMEM);

    // Fork a side stream for the independent query-projection chain.
    // kernel_launch is invoked exactly twice (correctness + capture), so
    // creating (and leaking) a stream/events per call is bounded and legal;
    // no device memory is involved. Events use DisableTiming (capture-safe).
    cudaStream_t s1;
    cudaStreamCreateWithFlags(&s1, cudaStreamNonBlocking);
    cudaEvent_t e0, e1;
    cudaEventCreateWithFlags(&e0, cudaEventDisableTiming);
    cudaEventCreateWithFlags(&e1, cudaEventDisableTiming);

    // weights -> bf16 (feeds both chains)
    wcvt<<<ceil_div(W0 + W1 + W2 + W3 + W4, 256), 256>>>(
        kp_w1, kp_w2, qp_w1, qp_w2, qp_w3, w1k, w2k, w1q, w2q, w3q);
    cudaEventRecord(e0, 0);
    cudaStreamWaitEvent(s1, e0, 0);

    // ---- query chain on s1 ----
    im2col3f<<<dim3(ceil_div(CQ * 3 * TDE / 2, 256), BB), 256, 0, s1>>>(
        queries, colq, CQ, TDE);
    gemm_bf16<64><<<dim3(ceil_div(TDE, GBN), ceil_div(QH1, 64), BB), 256, SM64, s1>>>(
        colq, w1q, qp_b1, qh1, CQ * 3, QH1, TDE, 1);
    gemm_bf16<64><<<dim3(ceil_div(TDE, GBN), ceil_div(CA, 64), BB), 256, SM64, s1>>>(
        qh1, w2q, qp_b2, qh2, QH1, CA, TDE, 1);
    gemm_bf16<64><<<dim3(ceil_div(TDE, GBN), ceil_div(CA, 64), BB), 256, SM64, s1>>>(
        qh2, w3q, qp_b3, qenc, CQ, CA, TDE, 0);
    cudaEventRecord(e1, s1);

    // ---- keys chain on the default stream ----
    im2col3f<<<dim3(ceil_div(CKCH * 3 * TEN / 2, 256), BB), 256>>>(keys, colk, CKCH, TEN);
    gemm128<<<dim3(TEN / 128, KH1 / 128, BB), 256, SM128>>>(
        colk, w1k, kp_b1, khid, CKCH * 3, KH1, TEN, 1);
    gemm_bf16<64><<<dim3(ceil_div(TEN, GBN), ceil_div(CA, 64), BB), 256, SM64>>>(
        khid, w2k, kp_b2, kenc, KH1, CA, TEN, 0);
    sqnorm_bf16<<<dim3(ceil_div(TEN, 256), BB), 256>>>(kenc, ksq, CA, TEN);

    // join: attn2 needs qenc (s1) and kenc/ksq (default)
    cudaStreamWaitEvent(0, e1, 0);
    attn2<<<dim3(ceil_div(TDE, AR), BB), 256, ATN_SMEM>>>(qenc, kenc, ksq, prior, out);
}